// round 10
// baseline (speedup 1.0000x reference)
#include <cuda_runtime.h>

#define NN 32
#define CC 64
#define OO 64
#define TT 512
#define VV 25
#define SS 3
#define RR 32
#define EPSV 1e-5f
#define TB 8            // t-tile per block
#define NTB (TT/TB)     // 64
#define TVW (TB*VV)     // 200
#define UPAD 32         // att u-row pad -> 128B line-aligned LDG.128
#define AOS (VV*UPAD)   // 800 floats per (n,s,o)
#define VTS 10          // vT row stride: [v][t] stride 10 (<=2-way dump conflicts)
#define OSTR (VV*VTS)   // 250 floats per o in vt
#define OQRT 16         // o's per block (quarter)

// ---- scratch ----
__device__ __align__(16) float g_xm[NN*CC*VV];
__device__ __align__(16) float g_att[NN*SS*OO*AOS];   // transposed [v][u], pads zero
__device__ __align__(16) float g_ybias[NN*OO*VV];
__device__ __align__(16) float g_w3t[SS*CC*OO];       // [s][c][o] (memcpy src)
__device__ __align__(16) float g_y[NN*OO*TT*VV];
__device__ float g_sum[OO], g_sumsq[OO], g_scale[OO], g_shift[OO];

// w3 transposed, served from the constant port (off L1TEX)
__constant__ __align__(16) float c_w3t[SS*CC*OO];     // 48 KB

// ---- f32x2 helpers ----
typedef unsigned long long ull;
__device__ __forceinline__ ull pk2(float a, float b) {
    ull r; asm("mov.b64 %0, {%1, %2};" : "=l"(r) : "f"(a), "f"(b)); return r;
}
__device__ __forceinline__ void upk2(ull p, float& a, float& b) {
    asm("mov.b64 {%0, %1}, %2;" : "=f"(a), "=f"(b) : "l"(p));
}
__device__ __forceinline__ ull fma2(ull a, ull b, ull c) {
    ull d; asm("fma.rn.f32x2 %0, %1, %2, %3;" : "=l"(d) : "l"(a), "l"(b), "l"(c)); return d;
}

// ---------------------------------------------------------------------------
// Kernel 1: xm mean over T; also transposes w3 into g_w3t
// ---------------------------------------------------------------------------
__global__ void k_xm(const float* __restrict__ x, const float* __restrict__ w3) {
    int idx = blockIdx.x * blockDim.x + threadIdx.x;
    if (idx < SS*CC*OO) {
        int o = idx % OO, c = (idx / OO) % CC, s = idx / (OO*CC);
        g_w3t[idx] = w3[(s*OO + o)*CC + c];
    }
    if (idx >= NN*CC*VV) return;
    int v  = idx % VV;
    int nc = idx / VV;
    const float* p = x + (size_t)nc * (TT*VV) + v;
    float a0=0.f, a1=0.f, a2=0.f, a3=0.f;
    #pragma unroll 4
    for (int t = 0; t < TT; t += 4) {
        a0 += p[(t+0)*VV]; a1 += p[(t+1)*VV];
        a2 += p[(t+2)*VV]; a3 += p[(t+3)*VV];
    }
    g_xm[idx] = (a0+a1+a2+a3) * (1.0f/(float)TT);
}

// ---------------------------------------------------------------------------
// Kernel 2: attention tensor, transposed+padded: g_att[(nso)][v*32+u]
// ---------------------------------------------------------------------------
__global__ void k_att(const float* __restrict__ w1, const float* __restrict__ b1,
                      const float* __restrict__ w2, const float* __restrict__ b2,
                      const float* __restrict__ w4, const float* __restrict__ b4,
                      const float* __restrict__ alpha, const float* __restrict__ A) {
    int n = blockIdx.x / SS, s = blockIdx.x % SS;
    __shared__ float xm_sm[CC*VV];
    __shared__ float q_sm[RR*VV];
    __shared__ float k_sm[RR*VV];
    __shared__ float w4_sm[OO*RR];
    __shared__ float b4_sm[OO];
    int tid = threadIdx.x;

    for (int i = tid; i < CC*VV; i += blockDim.x) xm_sm[i] = g_xm[n*CC*VV + i];
    for (int i = tid; i < OO*RR; i += blockDim.x) w4_sm[i] = w4[s*OO*RR + i];
    if (tid < OO) b4_sm[tid] = b4[s*OO + tid];
    __syncthreads();

    for (int e = tid; e < RR*VV; e += blockDim.x) {
        int r = e / VV, v = e % VV;
        const float* w1r = w1 + (s*RR + r)*CC;
        const float* w2r = w2 + (s*RR + r)*CC;
        float accq = b1[s*RR + r], acck = b2[s*RR + r];
        #pragma unroll 8
        for (int c = 0; c < CC; c++) {
            float xv = xm_sm[c*VV + v];
            accq = fmaf(w1r[c], xv, accq);
            acck = fmaf(w2r[c], xv, acck);
        }
        q_sm[e] = accq; k_sm[e] = acck;
    }
    __syncthreads();

    float al = alpha[s];
    for (int uv = tid; uv < VV*VV; uv += blockDim.x) {
        int u = uv / VV, v = uv % VV;
        float rel[RR];
        #pragma unroll
        for (int r = 0; r < RR; r++)
            rel[r] = fmaxf(q_sm[r*VV + u] - k_sm[r*VV + v], 0.f);
        float Auv = A[(s*VV + u)*VV + v];
        float* outp = g_att + (size_t)((n*SS + s)*OO) * AOS + v*UPAD + u;
        for (int o = 0; o < OO; o++) {
            float acc = 0.f;
            #pragma unroll
            for (int r = 0; r < RR; r++)
                acc = fmaf(w4_sm[o*RR + r], rel[r], acc);
            outp[o*AOS] = al*(acc + b4_sm[o]) + Auv;
        }
    }
}

// ---------------------------------------------------------------------------
// Kernel 3: ybias via one warp per (n,o), fully coalesced.
// ---------------------------------------------------------------------------
__global__ void k_ybias(const float* __restrict__ b3) {
    int n   = blockIdx.x >> 3;
    int oct = blockIdx.x & 7;
    int tid = threadIdx.x, w = tid >> 5, lane = tid & 31;
    if (blockIdx.x == 0) {
        if (tid < OO)             g_sum[tid] = 0.f;
        else if (tid < 2*OO)      g_sumsq[tid - OO] = 0.f;
    }
    int o = oct*8 + w;
    float acc = 0.f;
    #pragma unroll
    for (int s = 0; s < SS; s++) {
        const float* ap = g_att + (size_t)((n*SS + s)*OO + o) * AOS + lane;
        float rs = 0.f;
        #pragma unroll
        for (int v = 0; v < VV; v++) rs += ap[v*UPAD];
        acc = fmaf(b3[s*OO + o], rs, acc);
    }
    if (lane < VV) g_ybias[(n*OO + o)*VV + lane] = acc;
}

// ---------------------------------------------------------------------------
// Kernel 4 (main): o-QUARTER blocks for 3 blocks/SM (24 warps, was 16).
// 256 threads = 8 warps; block owns (n, t-tile 8, 16 o's).
// smem 67.2KB, regs capped 84 via __launch_bounds__(256,3).
// v-stage: warp = (o-octet q=w&1) x (tv-quarter h=w>>1). Lane owns one
//          contiguous tv-pair (lanes 0-24): 1 LDS.64/c; w o-pairs load as
//          ulonglong2 from CONSTANT port (2 uniform LDC.128/c); 8 f32x2/c.
// y-stage: warp owns local o-PAIR (2w, 2w+1): 2 att LDG.128 + 2 vt LDS.64
//          + 8 f32x2 per v.
// ---------------------------------------------------------------------------
#define SM_XS (CC*TVW)          // 12800
#define SM_VT (OQRT*OSTR)       // 4000
#define SMEM_FLOATS (SM_XS + SM_VT)   // 16800 floats = 67,200 B

__global__ void __launch_bounds__(256, 3)
k_main(const float* __restrict__ x) {
    extern __shared__ float sm[];
    float* xs = sm;
    float* vt = sm + SM_XS;

    int rem   = blockIdx.x % (NTB*4);
    int n     = blockIdx.x / (NTB*4);
    int tb    = rem >> 2;
    int obase = (rem & 3) * OQRT;
    int t0 = tb * TB;
    int tid = threadIdx.x, w = tid >> 5, lane = tid & 31;

    // stage x tile [c][200]
    float4* xs4 = (float4*)xs;
    for (int i = tid; i < CC*50; i += 256) {
        int c = i / 50, qd = i % 50;
        xs4[c*50 + qd] = *(const float4*)(x + (size_t)(n*CC + c)*(TT*VV) + t0*VV + qd*4);
    }

    // ---- v-stage lane constants (octet q, tv-quarter h) ----
    int q = w & 1, h = w >> 1;
    bool act = (lane < 25);
    int tvl = 50*h + 2*(act ? lane : 0);     // lane's contiguous tv-pair
    int sd0 = ((tvl)   % VV)*VTS + (tvl)/VV;
    int sd1 = ((tvl+1) % VV)*VTS + (tvl+1)/VV;

    // ---- y-stage lane constants ----
    int tp = lane >> 3, ug = lane & 7;

    // persistent y acc for the warp's o-pair, init with ybias
    // acc2[ol][j: local t in pair][p: u-pair]
    ull acc2[2][2][2];
    #pragma unroll
    for (int ol = 0; ol < 2; ol++) {
        const float* yb = g_ybias + (size_t)(n*OO + obase + 2*w + ol)*VV;
        #pragma unroll
        for (int p = 0; p < 2; p++) {
            int u0 = 4*ug + 2*p;
            float y0 = (u0   < VV) ? yb[u0]   : 0.f;
            float y1 = (u0+1 < VV) ? yb[u0+1] : 0.f;
            ull ybp = pk2(y0, y1);
            acc2[ol][0][p] = ybp; acc2[ol][1][p] = ybp;
        }
    }
    __syncthreads();

    for (int s = 0; s < SS; s++) {
        // ---- v-stage: 8 o's (4 o-pairs) x 1 tv-pair per lane ----
        ull acc[4][2];
        #pragma unroll
        for (int i = 0; i < 4; i++) { acc[i][0] = 0ull; acc[i][1] = 0ull; }

        const float* wbase = c_w3t + (s*CC)*OO + obase + 8*q;
        #pragma unroll 4
        for (int c = 0; c < CC; c++) {
            const ulonglong2* wp = (const ulonglong2*)(wbase + c*OO);
            ulonglong2 w01 = wp[0];   // o-pairs (0,1),(2,3)
            ulonglong2 w23 = wp[1];   // o-pairs (4,5),(6,7)
            ull xp = *(const ull*)(xs + c*TVW + tvl);
            float xa, xb; upk2(xp, xa, xb);
            ull xaa = pk2(xa, xa), xbb = pk2(xb, xb);
            acc[0][0]=fma2(w01.x,xaa,acc[0][0]); acc[0][1]=fma2(w01.x,xbb,acc[0][1]);
            acc[1][0]=fma2(w01.y,xaa,acc[1][0]); acc[1][1]=fma2(w01.y,xbb,acc[1][1]);
            acc[2][0]=fma2(w23.x,xaa,acc[2][0]); acc[2][1]=fma2(w23.x,xbb,acc[2][1]);
            acc[3][0]=fma2(w23.y,xaa,acc[3][0]); acc[3][1]=fma2(w23.y,xbb,acc[3][1]);
        }

        __syncthreads();   // prior y-stage reads of vt complete
        // ---- dump vT[o_loc][v][t]: acc[p] = o-pair (2p,2p+1) ----
        if (act) {
            #pragma unroll
            for (int p = 0; p < 4; p++) {
                float a0, a1, b0, b1;
                upk2(acc[p][0], a0, a1);   // tvl:   (o_lo, o_hi)
                upk2(acc[p][1], b0, b1);   // tvl+1: (o_lo, o_hi)
                float* d0 = vt + (8*q + 2*p) * OSTR;
                float* d1 = d0 + OSTR;
                d0[sd0] = a0; d1[sd0] = a1;
                d0[sd1] = b0; d1[sd1] = b1;
            }
        }
        __syncthreads();

        // ---- y-stage: warp's o-pair, 2 att streams ----
        const float* dvp0 = vt + (2*w + 0)*OSTR + 2*tp;
        const float* dvp1 = vt + (2*w + 1)*OSTR + 2*tp;
        const float* agb  = g_att + (size_t)((n*SS + s)*OO + obase + 2*w)*AOS + 4*ug;
        #pragma unroll
        for (int v = 0; v < VV; v++) {
            ulonglong2 at0 = *(const ulonglong2*)(agb + v*UPAD);
            ulonglong2 at1 = *(const ulonglong2*)(agb + AOS + v*UPAD);
            float2 vb0 = *(const float2*)(dvp0 + v*VTS);
            float2 vb1 = *(const float2*)(dvp1 + v*VTS);

            ull va, vbb;
            va = pk2(vb0.x, vb0.x); vbb = pk2(vb0.y, vb0.y);
            acc2[0][0][0] = fma2(at0.x, va,  acc2[0][0][0]);
            acc2[0][0][1] = fma2(at0.y, va,  acc2[0][0][1]);
            acc2[0][1][0] = fma2(at0.x, vbb, acc2[0][1][0]);
            acc2[0][1][1] = fma2(at0.y, vbb, acc2[0][1][1]);
            va = pk2(vb1.x, vb1.x); vbb = pk2(vb1.y, vb1.y);
            acc2[1][0][0] = fma2(at1.x, va,  acc2[1][0][0]);
            acc2[1][0][1] = fma2(at1.y, va,  acc2[1][0][1]);
            acc2[1][1][0] = fma2(at1.x, vbb, acc2[1][1][0]);
            acc2[1][1][1] = fma2(at1.y, vbb, acc2[1][1][1]);
        }
    }

    // ---- epilogue: write y, accumulate BN stats ----
    #pragma unroll
    for (int ol = 0; ol < 2; ol++) {
        int o = obase + 2*w + ol;
        float ps = 0.f, pss = 0.f;
        #pragma unroll
        for (int j = 0; j < 2; j++) {
            int t = 2*tp + j;
            float uv0, uv1, uv2, uv3;
            upk2(acc2[ol][j][0], uv0, uv1);
            upk2(acc2[ol][j][1], uv2, uv3);
            float vals[4] = {uv0, uv1, uv2, uv3};
            float* yp = g_y + ((size_t)(n*OO + o)*TT + t0 + t)*VV;
            #pragma unroll
            for (int i = 0; i < 4; i++) {
                int u = 4*ug + i;
                if (u < VV) {
                    yp[u] = vals[i];
                    ps  += vals[i];
                    pss += vals[i]*vals[i];
                }
            }
        }
        #pragma unroll
        for (int off = 16; off > 0; off >>= 1) {
            ps  += __shfl_xor_sync(0xffffffffu, ps,  off);
            pss += __shfl_xor_sync(0xffffffffu, pss, off);
        }
        if (lane == 0) {
            atomicAdd(&g_sum[o],   ps);
            atomicAdd(&g_sumsq[o], pss);
        }
    }
}

// ---------------------------------------------------------------------------
// Kernel 5: BN scale/shift
// ---------------------------------------------------------------------------
__global__ void k_bnp(const float* __restrict__ gamma, const float* __restrict__ beta) {
    int o = threadIdx.x;
    if (o < OO) {
        float cnt = (float)(NN*TT*VV);
        float mu  = g_sum[o] / cnt;
        float var = g_sumsq[o] / cnt - mu*mu;
        float sc  = gamma[o] * rsqrtf(var + EPSV);
        g_scale[o] = sc;
        g_shift[o] = beta[o] - mu*sc;
    }
}

// ---------------------------------------------------------------------------
// Kernel 6: out = relu(y) + y*scale + shift + x
// ---------------------------------------------------------------------------
__global__ void k_final(const float* __restrict__ x, float* __restrict__ out) {
    const int total4 = NN*OO*TT*VV / 4;
    for (int i = blockIdx.x*blockDim.x + threadIdx.x; i < total4; i += gridDim.x*blockDim.x) {
        int c = (i / (TT*VV/4)) % OO;
        float sc = g_scale[c], sh = g_shift[c];
        float4 y4 = ((const float4*)g_y)[i];
        float4 x4 = ((const float4*)x)[i];
        float4 r;
        r.x = fmaxf(y4.x, 0.f) + fmaf(y4.x, sc, sh) + x4.x;
        r.y = fmaxf(y4.y, 0.f) + fmaf(y4.y, sc, sh) + x4.y;
        r.z = fmaxf(y4.z, 0.f) + fmaf(y4.z, sc, sh) + x4.z;
        r.w = fmaxf(y4.w, 0.f) + fmaf(y4.w, sc, sh) + x4.w;
        ((float4*)out)[i] = r;
    }
}

// ---------------------------------------------------------------------------
extern "C" void kernel_launch(void* const* d_in, const int* in_sizes, int n_in,
                              void* d_out, int out_size) {
    (void)in_sizes; (void)n_in; (void)out_size;
    const float* x     = (const float*)d_in[0];
    const float* A     = (const float*)d_in[1];
    const float* w1    = (const float*)d_in[2];
    const float* b1    = (const float*)d_in[3];
    const float* w2    = (const float*)d_in[4];
    const float* b2    = (const float*)d_in[5];
    const float* w3    = (const float*)d_in[6];
    const float* b3    = (const float*)d_in[7];
    const float* w4    = (const float*)d_in[8];
    const float* b4    = (const float*)d_in[9];
    const float* alpha = (const float*)d_in[10];
    const float* gamma = (const float*)d_in[11];
    const float* beta  = (const float*)d_in[12];
    float* out = (float*)d_out;

    static const int smem_bytes = SMEM_FLOATS * (int)sizeof(float);
    cudaFuncSetAttribute(k_main, cudaFuncAttributeMaxDynamicSharedMemorySize, smem_bytes);

    void* w3t_dev = nullptr;
    cudaGetSymbolAddress(&w3t_dev, g_w3t);

    k_xm   <<< (NN*CC*VV + 255)/256, 256 >>>(x, w3);
    cudaMemcpyToSymbolAsync(c_w3t, w3t_dev, SS*CC*OO*sizeof(float), 0,
                            cudaMemcpyDeviceToDevice, 0);
    k_att  <<< NN*SS, 256 >>>(w1, b1, w2, b2, w4, b4, alpha, A);
    k_ybias<<< NN*8, 256 >>>(b3);
    k_main <<< NN*NTB*4, 256, smem_bytes >>>(x);
    k_bnp  <<< 1, 64 >>>(gamma, beta);
    k_final<<< 2048, 256 >>>(x, out);
}

// round 11
// speedup vs baseline: 1.1882x; 1.1882x over previous
#include <cuda_runtime.h>

#define NN 32
#define CC 64
#define OO 64
#define TT 512
#define VV 25
#define SS 3
#define RR 32
#define EPSV 1e-5f
#define TB 8            // t-tile per block
#define NTB (TT/TB)     // 64
#define TVW (TB*VV)     // 200
#define UPAD 32         // att u-row pad -> 128B line-aligned LDG.128
#define AOS (VV*UPAD)   // 800 floats per (n,s,o)
#define VTS 10          // vT row stride: [v][t] stride 10 (<=2-way dump conflicts)
#define OSTR (VV*VTS)   // 250 floats per o in vt
#define OHALF 32        // o's per block

// ---- scratch ----
__device__ __align__(16) float g_xm[NN*CC*VV];
__device__ __align__(16) float g_att[NN*SS*OO*AOS];   // transposed [v][u], pads zero
__device__ __align__(16) float g_ybias[NN*OO*VV];
__device__ __align__(16) float g_w3t[SS*CC*OO];       // [s][c][o] (memcpy src)
__device__ __align__(16) float g_y[NN*OO*TT*VV];
__device__ float g_sum[OO], g_sumsq[OO], g_scale[OO], g_shift[OO];

// w3 transposed, served from the constant port (off L1TEX)
__constant__ __align__(16) float c_w3t[SS*CC*OO];     // 48 KB

// ---- f32x2 helpers ----
typedef unsigned long long ull;
__device__ __forceinline__ ull pk2(float a, float b) {
    ull r; asm("mov.b64 %0, {%1, %2};" : "=l"(r) : "f"(a), "f"(b)); return r;
}
__device__ __forceinline__ void upk2(ull p, float& a, float& b) {
    asm("mov.b64 {%0, %1}, %2;" : "=f"(a), "=f"(b) : "l"(p));
}
__device__ __forceinline__ ull fma2(ull a, ull b, ull c) {
    ull d; asm("fma.rn.f32x2 %0, %1, %2, %3;" : "=l"(d) : "l"(a), "l"(b), "l"(c)); return d;
}

// ---------------------------------------------------------------------------
// Kernel 1 (rewritten): xm mean over T — one block per (n,c), coalesced rows,
// warp per 64-t chunk with lane=v, smem tree reduce. Also transposes w3
// (first 48 blocks carry one 256-elem chunk each).
// ---------------------------------------------------------------------------
__global__ void k_xm(const float* __restrict__ x, const float* __restrict__ w3) {
    int bid = blockIdx.x;              // (n*CC + c), 2048 blocks
    int tid = threadIdx.x, w = tid >> 5, lane = tid & 31;

    if (bid < 48) {                    // 48*256 = SS*CC*OO exactly
        int idx = bid*256 + tid;
        int o = idx % OO, c = (idx / OO) % CC, s = idx / (OO*CC);
        g_w3t[idx] = w3[(s*OO + o)*CC + c];
    }

    __shared__ float part[8][VV];
    const float* base = x + (size_t)bid * (TT*VV);
    if (lane < VV) {
        const float* p = base + (w*64)*VV + lane;
        float a0=0.f, a1=0.f, a2=0.f, a3=0.f;
        #pragma unroll 4
        for (int t = 0; t < 64; t += 4) {
            a0 += p[(t+0)*VV]; a1 += p[(t+1)*VV];
            a2 += p[(t+2)*VV]; a3 += p[(t+3)*VV];
        }
        part[w][lane] = (a0+a1)+(a2+a3);
    }
    __syncthreads();
    if (tid < VV) {
        float s2 = 0.f;
        #pragma unroll
        for (int ww = 0; ww < 8; ww++) s2 += part[ww][tid];
        g_xm[bid*VV + tid] = s2 * (1.0f/(float)TT);
    }
}

// ---------------------------------------------------------------------------
// Kernel 2 (o-split x4): attention tensor, transposed+padded g_att[(nso)][v*32+u]
// block = (n, s, o-slice of 16); q/k recomputed per slice (cheap).
// ---------------------------------------------------------------------------
#define OSL 16
__global__ void k_att(const float* __restrict__ w1, const float* __restrict__ b1,
                      const float* __restrict__ w2, const float* __restrict__ b2,
                      const float* __restrict__ w4, const float* __restrict__ b4,
                      const float* __restrict__ alpha, const float* __restrict__ A) {
    int og = blockIdx.x & 3;
    int ns = blockIdx.x >> 2;
    int n = ns / SS, s = ns % SS;
    __shared__ float xm_sm[CC*VV];
    __shared__ float q_sm[RR*VV];
    __shared__ float k_sm[RR*VV];
    __shared__ float w4_sm[OSL*RR];
    __shared__ float b4_sm[OSL];
    int tid = threadIdx.x;

    for (int i = tid; i < CC*VV; i += blockDim.x) xm_sm[i] = g_xm[n*CC*VV + i];
    for (int i = tid; i < OSL*RR; i += blockDim.x) w4_sm[i] = w4[s*OO*RR + og*OSL*RR + i];
    if (tid < OSL) b4_sm[tid] = b4[s*OO + og*OSL + tid];
    __syncthreads();

    for (int e = tid; e < RR*VV; e += blockDim.x) {
        int r = e / VV, v = e % VV;
        const float* w1r = w1 + (s*RR + r)*CC;
        const float* w2r = w2 + (s*RR + r)*CC;
        float accq = b1[s*RR + r], acck = b2[s*RR + r];
        #pragma unroll 8
        for (int c = 0; c < CC; c++) {
            float xv = xm_sm[c*VV + v];
            accq = fmaf(w1r[c], xv, accq);
            acck = fmaf(w2r[c], xv, acck);
        }
        q_sm[e] = accq; k_sm[e] = acck;
    }
    __syncthreads();

    float al = alpha[s];
    for (int uv = tid; uv < VV*VV; uv += blockDim.x) {
        int u = uv / VV, v = uv % VV;
        float rel[RR];
        #pragma unroll
        for (int r = 0; r < RR; r++)
            rel[r] = fmaxf(q_sm[r*VV + u] - k_sm[r*VV + v], 0.f);
        float Auv = A[(s*VV + u)*VV + v];
        float* outp = g_att + (size_t)((n*SS + s)*OO + og*OSL) * AOS + v*UPAD + u;
        for (int o = 0; o < OSL; o++) {
            float acc = 0.f;
            #pragma unroll
            for (int r = 0; r < RR; r++)
                acc = fmaf(w4_sm[o*RR + r], rel[r], acc);
            outp[o*AOS] = al*(acc + b4_sm[o]) + Auv;
        }
    }
}

// ---------------------------------------------------------------------------
// Kernel 3: ybias via one warp per (n,o), fully coalesced.
// ---------------------------------------------------------------------------
__global__ void k_ybias(const float* __restrict__ b3) {
    int n   = blockIdx.x >> 3;
    int oct = blockIdx.x & 7;
    int tid = threadIdx.x, w = tid >> 5, lane = tid & 31;
    if (blockIdx.x == 0) {
        if (tid < OO)             g_sum[tid] = 0.f;
        else if (tid < 2*OO)      g_sumsq[tid - OO] = 0.f;
    }
    int o = oct*8 + w;
    float acc = 0.f;
    #pragma unroll
    for (int s = 0; s < SS; s++) {
        const float* ap = g_att + (size_t)((n*SS + s)*OO + o) * AOS + lane;
        float rs = 0.f;
        #pragma unroll
        for (int v = 0; v < VV; v++) rs += ap[v*UPAD];
        acc = fmaf(b3[s*OO + o], rs, acc);
    }
    if (lane < VV) g_ybias[(n*OO + o)*VV + lane] = acc;
}

// ---------------------------------------------------------------------------
// Kernel 4 (main): EXACT round-9 version (proven 523us). Untouched.
// ---------------------------------------------------------------------------
#define SM_XS (CC*TVW)          // 12800
#define SM_VT (OHALF*OSTR)      // 8000
#define SMEM_FLOATS (SM_XS + SM_VT)   // 20800 floats = 83,200 B

__global__ void __launch_bounds__(256, 2)
k_main(const float* __restrict__ x) {
    extern __shared__ float sm[];
    float* xs = sm;
    float* vt = sm + SM_XS;

    int rem  = blockIdx.x % (NTB*2);
    int n    = blockIdx.x / (NTB*2);
    int tb   = rem >> 1;
    int obase = (rem & 1) * OHALF;
    int t0 = tb * TB;
    int tid = threadIdx.x, w = tid >> 5, lane = tid & 31;

    // stage x tile [c][200]
    float4* xs4 = (float4*)xs;
    for (int i = tid; i < CC*50; i += 256) {
        int c = i / 50, qd = i % 50;
        xs4[c*50 + qd] = *(const float4*)(x + (size_t)(n*CC + c)*(TT*VV) + t0*VV + qd*4);
    }

    // ---- v-stage lane constants (octet q, half h) ----
    int q = w & 3, h = w >> 2;
    bool hasB = (lane < 18);
    int offA = 100*h + 2*lane;
    int offB = hasB ? (offA + 64) : offA;
    int tvA  = offA;
    int tvB  = offA + 64;
    int sA0 = (tvA % VV)*VTS + tvA/VV;
    int sA1 = ((tvA+1) % VV)*VTS + (tvA+1)/VV;
    int sB0 = hasB ? ((tvB % VV)*VTS + tvB/VV) : 0;
    int sB1 = hasB ? (((tvB+1) % VV)*VTS + (tvB+1)/VV) : 0;

    // ---- y-stage lane constants ----
    int tp = lane >> 3, ug = lane & 7;

    // persistent y acc (f32x2 over u-pairs), init with ybias
    ull acc2[4][2][2];
    #pragma unroll
    for (int oq = 0; oq < 4; oq++) {
        const float* yb = g_ybias + (size_t)(n*OO + obase + 4*w + oq)*VV;
        #pragma unroll
        for (int p = 0; p < 2; p++) {
            int u0 = 4*ug + 2*p;
            float y0 = (u0   < VV) ? yb[u0]   : 0.f;
            float y1 = (u0+1 < VV) ? yb[u0+1] : 0.f;
            ull ybp = pk2(y0, y1);
            acc2[oq][0][p] = ybp; acc2[oq][1][p] = ybp;
        }
    }
    __syncthreads();

    for (int s = 0; s < SS; s++) {
        // ---- v-stage: 8 o's x 2 tv-pairs; w3 via constant port ----
        ull acc[8][2];
        #pragma unroll
        for (int i = 0; i < 8; i++) { acc[i][0] = 0ull; acc[i][1] = 0ull; }

        int wbase = (s*CC)*OO + obase + 8*q;
        #pragma unroll 4
        for (int c = 0; c < CC; c++) {
            float4 wA4 = *(const float4*)(c_w3t + wbase + c*OO);
            float4 wB4 = *(const float4*)(c_w3t + wbase + c*OO + 4);
            const float* xr = xs + c*TVW;
            ull xA = *(const ull*)(xr + offA);
            ull xB = *(const ull*)(xr + offB);
            ull w0 = pk2(wA4.x, wA4.x), w1 = pk2(wA4.y, wA4.y);
            ull w2 = pk2(wA4.z, wA4.z), w3s = pk2(wA4.w, wA4.w);
            ull w4s = pk2(wB4.x, wB4.x), w5 = pk2(wB4.y, wB4.y);
            ull w6 = pk2(wB4.z, wB4.z), w7 = pk2(wB4.w, wB4.w);
            acc[0][0]=fma2(w0,xA,acc[0][0]);  acc[0][1]=fma2(w0,xB,acc[0][1]);
            acc[1][0]=fma2(w1,xA,acc[1][0]);  acc[1][1]=fma2(w1,xB,acc[1][1]);
            acc[2][0]=fma2(w2,xA,acc[2][0]);  acc[2][1]=fma2(w2,xB,acc[2][1]);
            acc[3][0]=fma2(w3s,xA,acc[3][0]); acc[3][1]=fma2(w3s,xB,acc[3][1]);
            acc[4][0]=fma2(w4s,xA,acc[4][0]); acc[4][1]=fma2(w4s,xB,acc[4][1]);
            acc[5][0]=fma2(w5,xA,acc[5][0]);  acc[5][1]=fma2(w5,xB,acc[5][1]);
            acc[6][0]=fma2(w6,xA,acc[6][0]);  acc[6][1]=fma2(w6,xB,acc[6][1]);
            acc[7][0]=fma2(w7,xA,acc[7][0]);  acc[7][1]=fma2(w7,xB,acc[7][1]);
        }

        __syncthreads();   // prior y-stage reads of vt complete
        // ---- dump vT[o_loc][v][t] ----
        #pragma unroll
        for (int i = 0; i < 8; i++) {
            float* d = vt + (8*q + i) * OSTR;
            float lo, hi;
            upk2(acc[i][0], lo, hi);
            d[sA0] = lo; d[sA1] = hi;
            if (hasB) {
                upk2(acc[i][1], lo, hi);
                d[sB0] = lo; d[sB1] = hi;
            }
        }
        __syncthreads();

        // ---- y-stage: all 4 oq interleaved -> 4 independent att streams ----
        const float* dvp0 = vt + (4*w + 0)*OSTR + 2*tp;
        const float* dvp1 = vt + (4*w + 1)*OSTR + 2*tp;
        const float* dvp2 = vt + (4*w + 2)*OSTR + 2*tp;
        const float* dvp3 = vt + (4*w + 3)*OSTR + 2*tp;
        const float* agb = g_att + (size_t)((n*SS + s)*OO + obase + 4*w)*AOS + 4*ug;
        #pragma unroll
        for (int v = 0; v < VV; v++) {
            ulonglong2 at0 = *(const ulonglong2*)(agb + 0*AOS + v*UPAD);
            ulonglong2 at1 = *(const ulonglong2*)(agb + 1*AOS + v*UPAD);
            ulonglong2 at2 = *(const ulonglong2*)(agb + 2*AOS + v*UPAD);
            ulonglong2 at3 = *(const ulonglong2*)(agb + 3*AOS + v*UPAD);
            float2 vb0 = *(const float2*)(dvp0 + v*VTS);
            float2 vb1 = *(const float2*)(dvp1 + v*VTS);
            float2 vb2 = *(const float2*)(dvp2 + v*VTS);
            float2 vb3 = *(const float2*)(dvp3 + v*VTS);

            ull va, vbb;
            va = pk2(vb0.x, vb0.x); vbb = pk2(vb0.y, vb0.y);
            acc2[0][0][0] = fma2(at0.x, va,  acc2[0][0][0]);
            acc2[0][0][1] = fma2(at0.y, va,  acc2[0][0][1]);
            acc2[0][1][0] = fma2(at0.x, vbb, acc2[0][1][0]);
            acc2[0][1][1] = fma2(at0.y, vbb, acc2[0][1][1]);
            va = pk2(vb1.x, vb1.x); vbb = pk2(vb1.y, vb1.y);
            acc2[1][0][0] = fma2(at1.x, va,  acc2[1][0][0]);
            acc2[1][0][1] = fma2(at1.y, va,  acc2[1][0][1]);
            acc2[1][1][0] = fma2(at1.x, vbb, acc2[1][1][0]);
            acc2[1][1][1] = fma2(at1.y, vbb, acc2[1][1][1]);
            va = pk2(vb2.x, vb2.x); vbb = pk2(vb2.y, vb2.y);
            acc2[2][0][0] = fma2(at2.x, va,  acc2[2][0][0]);
            acc2[2][0][1] = fma2(at2.y, va,  acc2[2][0][1]);
            acc2[2][1][0] = fma2(at2.x, vbb, acc2[2][1][0]);
            acc2[2][1][1] = fma2(at2.y, vbb, acc2[2][1][1]);
            va = pk2(vb3.x, vb3.x); vbb = pk2(vb3.y, vb3.y);
            acc2[3][0][0] = fma2(at3.x, va,  acc2[3][0][0]);
            acc2[3][0][1] = fma2(at3.y, va,  acc2[3][0][1]);
            acc2[3][1][0] = fma2(at3.x, vbb, acc2[3][1][0]);
            acc2[3][1][1] = fma2(at3.y, vbb, acc2[3][1][1]);
        }
    }

    // ---- epilogue: write y, accumulate BN stats ----
    #pragma unroll
    for (int oq = 0; oq < 4; oq++) {
        int o = obase + 4*w + oq;
        float ps = 0.f, pss = 0.f;
        #pragma unroll
        for (int j = 0; j < 2; j++) {
            int t = 2*tp + j;
            float uv0, uv1, uv2, uv3;
            upk2(acc2[oq][j][0], uv0, uv1);
            upk2(acc2[oq][j][1], uv2, uv3);
            float vals[4] = {uv0, uv1, uv2, uv3};
            float* yp = g_y + ((size_t)(n*OO + o)*TT + t0 + t)*VV;
            #pragma unroll
            for (int i = 0; i < 4; i++) {
                int u = 4*ug + i;
                if (u < VV) {
                    yp[u] = vals[i];
                    ps  += vals[i];
                    pss += vals[i]*vals[i];
                }
            }
        }
        #pragma unroll
        for (int off = 16; off > 0; off >>= 1) {
            ps  += __shfl_xor_sync(0xffffffffu, ps,  off);
            pss += __shfl_xor_sync(0xffffffffu, pss, off);
        }
        if (lane == 0) {
            atomicAdd(&g_sum[o],   ps);
            atomicAdd(&g_sumsq[o], pss);
        }
    }
}

// ---------------------------------------------------------------------------
// Kernel 5: BN scale/shift
// ---------------------------------------------------------------------------
__global__ void k_bnp(const float* __restrict__ gamma, const float* __restrict__ beta) {
    int o = threadIdx.x;
    if (o < OO) {
        float cnt = (float)(NN*TT*VV);
        float mu  = g_sum[o] / cnt;
        float var = g_sumsq[o] / cnt - mu*mu;
        float sc  = gamma[o] * rsqrtf(var + EPSV);
        g_scale[o] = sc;
        g_shift[o] = beta[o] - mu*sc;
    }
}

// ---------------------------------------------------------------------------
// Kernel 6: out = relu(y) + y*scale + shift + x
// ---------------------------------------------------------------------------
__global__ void k_final(const float* __restrict__ x, float* __restrict__ out) {
    const int total4 = NN*OO*TT*VV / 4;
    for (int i = blockIdx.x*blockDim.x + threadIdx.x; i < total4; i += gridDim.x*blockDim.x) {
        int c = (i / (TT*VV/4)) % OO;
        float sc = g_scale[c], sh = g_shift[c];
        float4 y4 = ((const float4*)g_y)[i];
        float4 x4 = ((const float4*)x)[i];
        float4 r;
        r.x = fmaxf(y4.x, 0.f) + fmaf(y4.x, sc, sh) + x4.x;
        r.y = fmaxf(y4.y, 0.f) + fmaf(y4.y, sc, sh) + x4.y;
        r.z = fmaxf(y4.z, 0.f) + fmaf(y4.z, sc, sh) + x4.z;
        r.w = fmaxf(y4.w, 0.f) + fmaf(y4.w, sc, sh) + x4.w;
        ((float4*)out)[i] = r;
    }
}

// ---------------------------------------------------------------------------
extern "C" void kernel_launch(void* const* d_in, const int* in_sizes, int n_in,
                              void* d_out, int out_size) {
    (void)in_sizes; (void)n_in; (void)out_size;
    const float* x     = (const float*)d_in[0];
    const float* A     = (const float*)d_in[1];
    const float* w1    = (const float*)d_in[2];
    const float* b1    = (const float*)d_in[3];
    const float* w2    = (const float*)d_in[4];
    const float* b2    = (const float*)d_in[5];
    const float* w3    = (const float*)d_in[6];
    const float* b3    = (const float*)d_in[7];
    const float* w4    = (const float*)d_in[8];
    const float* b4    = (const float*)d_in[9];
    const float* alpha = (const float*)d_in[10];
    const float* gamma = (const float*)d_in[11];
    const float* beta  = (const float*)d_in[12];
    float* out = (float*)d_out;

    static const int smem_bytes = SMEM_FLOATS * (int)sizeof(float);
    cudaFuncSetAttribute(k_main, cudaFuncAttributeMaxDynamicSharedMemorySize, smem_bytes);

    void* w3t_dev = nullptr;
    cudaGetSymbolAddress(&w3t_dev, g_w3t);

    k_xm   <<< NN*CC, 256 >>>(x, w3);
    cudaMemcpyToSymbolAsync(c_w3t, w3t_dev, SS*CC*OO*sizeof(float), 0,
                            cudaMemcpyDeviceToDevice, 0);
    k_att  <<< NN*SS*4, 256 >>>(w1, b1, w2, b2, w4, b4, alpha, A);
    k_ybias<<< NN*8, 256 >>>(b3);
    k_main <<< NN*NTB*2, 256, smem_bytes >>>(x);
    k_bnp  <<< 1, 64 >>>(gamma, beta);
    k_final<<< 4096, 256 >>>(x, out);
}

// round 12
// speedup vs baseline: 1.2162x; 1.0236x over previous
#include <cuda_runtime.h>
#include <cuda_fp16.h>

#define NN 32
#define CC 64
#define OO 64
#define TT 512
#define VV 25
#define SS 3
#define RR 32
#define EPSV 1e-5f
#define TB 8            // t-tile per block
#define NTB (TT/TB)     // 64
#define TVW (TB*VV)     // 200
#define UPAD 32         // att u-row pad -> 128B line-aligned LDG.128
#define AOS (VV*UPAD)   // 800 floats per (n,s,o)
#define VTS 10          // vT row stride: [v][t] stride 10 (<=2-way dump conflicts)
#define OSTR (VV*VTS)   // 250 floats per o in vt
#define OHALF 32        // o's per block

// ---- scratch ----
__device__ __align__(16) float g_xm[NN*CC*VV];
__device__ __align__(16) float g_att[NN*SS*OO*AOS];   // transposed [v][u], pads zero
__device__ __align__(16) float g_ybias[NN*OO*VV];
__device__ __align__(16) float g_w3t[SS*CC*OO];       // [s][c][o] (memcpy src)
__device__ __align__(16) __half g_yh[NN*OO*TT*VV];    // y in fp16 (halves HBM round trip)
__device__ float g_sum[OO], g_sumsq[OO];

// w3 transposed, served from the constant port (off L1TEX)
__constant__ __align__(16) float c_w3t[SS*CC*OO];     // 48 KB

// ---- f32x2 helpers ----
typedef unsigned long long ull;
__device__ __forceinline__ ull pk2(float a, float b) {
    ull r; asm("mov.b64 %0, {%1, %2};" : "=l"(r) : "f"(a), "f"(b)); return r;
}
__device__ __forceinline__ void upk2(ull p, float& a, float& b) {
    asm("mov.b64 {%0, %1}, %2;" : "=f"(a), "=f"(b) : "l"(p));
}
__device__ __forceinline__ ull fma2(ull a, ull b, ull c) {
    ull d; asm("fma.rn.f32x2 %0, %1, %2, %3;" : "=l"(d) : "l"(a), "l"(b), "l"(c)); return d;
}

// ---------------------------------------------------------------------------
// Kernel 1: xm mean over T — one block per (n,c), coalesced rows,
// warp per 64-t chunk with lane=v, smem tree reduce. Also transposes w3.
// ---------------------------------------------------------------------------
__global__ void k_xm(const float* __restrict__ x, const float* __restrict__ w3) {
    int bid = blockIdx.x;              // (n*CC + c), 2048 blocks
    int tid = threadIdx.x, w = tid >> 5, lane = tid & 31;

    if (bid < 48) {                    // 48*256 = SS*CC*OO exactly
        int idx = bid*256 + tid;
        int o = idx % OO, c = (idx / OO) % CC, s = idx / (OO*CC);
        g_w3t[idx] = w3[(s*OO + o)*CC + c];
    }

    __shared__ float part[8][VV];
    const float* base = x + (size_t)bid * (TT*VV);
    if (lane < VV) {
        const float* p = base + (w*64)*VV + lane;
        float a0=0.f, a1=0.f, a2=0.f, a3=0.f;
        #pragma unroll 4
        for (int t = 0; t < 64; t += 4) {
            a0 += p[(t+0)*VV]; a1 += p[(t+1)*VV];
            a2 += p[(t+2)*VV]; a3 += p[(t+3)*VV];
        }
        part[w][lane] = (a0+a1)+(a2+a3);
    }
    __syncthreads();
    if (tid < VV) {
        float s2 = 0.f;
        #pragma unroll
        for (int ww = 0; ww < 8; ww++) s2 += part[ww][tid];
        g_xm[bid*VV + tid] = s2 * (1.0f/(float)TT);
    }
}

// ---------------------------------------------------------------------------
// Kernel 2 (o-split x4): attention tensor, transposed+padded g_att[(nso)][v*32+u]
// ---------------------------------------------------------------------------
#define OSL 16
__global__ void k_att(const float* __restrict__ w1, const float* __restrict__ b1,
                      const float* __restrict__ w2, const float* __restrict__ b2,
                      const float* __restrict__ w4, const float* __restrict__ b4,
                      const float* __restrict__ alpha, const float* __restrict__ A) {
    int og = blockIdx.x & 3;
    int ns = blockIdx.x >> 2;
    int n = ns / SS, s = ns % SS;
    __shared__ float xm_sm[CC*VV];
    __shared__ float q_sm[RR*VV];
    __shared__ float k_sm[RR*VV];
    __shared__ float w4_sm[OSL*RR];
    __shared__ float b4_sm[OSL];
    int tid = threadIdx.x;

    for (int i = tid; i < CC*VV; i += blockDim.x) xm_sm[i] = g_xm[n*CC*VV + i];
    for (int i = tid; i < OSL*RR; i += blockDim.x) w4_sm[i] = w4[s*OO*RR + og*OSL*RR + i];
    if (tid < OSL) b4_sm[tid] = b4[s*OO + og*OSL + tid];
    __syncthreads();

    for (int e = tid; e < RR*VV; e += blockDim.x) {
        int r = e / VV, v = e % VV;
        const float* w1r = w1 + (s*RR + r)*CC;
        const float* w2r = w2 + (s*RR + r)*CC;
        float accq = b1[s*RR + r], acck = b2[s*RR + r];
        #pragma unroll 8
        for (int c = 0; c < CC; c++) {
            float xv = xm_sm[c*VV + v];
            accq = fmaf(w1r[c], xv, accq);
            acck = fmaf(w2r[c], xv, acck);
        }
        q_sm[e] = accq; k_sm[e] = acck;
    }
    __syncthreads();

    float al = alpha[s];
    for (int uv = tid; uv < VV*VV; uv += blockDim.x) {
        int u = uv / VV, v = uv % VV;
        float rel[RR];
        #pragma unroll
        for (int r = 0; r < RR; r++)
            rel[r] = fmaxf(q_sm[r*VV + u] - k_sm[r*VV + v], 0.f);
        float Auv = A[(s*VV + u)*VV + v];
        float* outp = g_att + (size_t)((n*SS + s)*OO + og*OSL) * AOS + v*UPAD + u;
        for (int o = 0; o < OSL; o++) {
            float acc = 0.f;
            #pragma unroll
            for (int r = 0; r < RR; r++)
                acc = fmaf(w4_sm[o*RR + r], rel[r], acc);
            outp[o*AOS] = al*(acc + b4_sm[o]) + Auv;
        }
    }
}

// ---------------------------------------------------------------------------
// Kernel 3: ybias via one warp per (n,o), fully coalesced; zeroes BN stats.
// ---------------------------------------------------------------------------
__global__ void k_ybias(const float* __restrict__ b3) {
    int n   = blockIdx.x >> 3;
    int oct = blockIdx.x & 7;
    int tid = threadIdx.x, w = tid >> 5, lane = tid & 31;
    if (blockIdx.x == 0) {
        if (tid < OO)             g_sum[tid] = 0.f;
        else if (tid < 2*OO)      g_sumsq[tid - OO] = 0.f;
    }
    int o = oct*8 + w;
    float acc = 0.f;
    #pragma unroll
    for (int s = 0; s < SS; s++) {
        const float* ap = g_att + (size_t)((n*SS + s)*OO + o) * AOS + lane;
        float rs = 0.f;
        #pragma unroll
        for (int v = 0; v < VV; v++) rs += ap[v*UPAD];
        acc = fmaf(b3[s*OO + o], rs, acc);
    }
    if (lane < VV) g_ybias[(n*OO + o)*VV + lane] = acc;
}

// ---------------------------------------------------------------------------
// Kernel 4 (main): round-9 version (proven 521us); only the epilogue's y
// stores are fp16 now.
// ---------------------------------------------------------------------------
#define SM_XS (CC*TVW)          // 12800
#define SM_VT (OHALF*OSTR)      // 8000
#define SMEM_FLOATS (SM_XS + SM_VT)   // 20800 floats = 83,200 B

__global__ void __launch_bounds__(256, 2)
k_main(const float* __restrict__ x) {
    extern __shared__ float sm[];
    float* xs = sm;
    float* vt = sm + SM_XS;

    int rem  = blockIdx.x % (NTB*2);
    int n    = blockIdx.x / (NTB*2);
    int tb   = rem >> 1;
    int obase = (rem & 1) * OHALF;
    int t0 = tb * TB;
    int tid = threadIdx.x, w = tid >> 5, lane = tid & 31;

    // stage x tile [c][200]
    float4* xs4 = (float4*)xs;
    for (int i = tid; i < CC*50; i += 256) {
        int c = i / 50, qd = i % 50;
        xs4[c*50 + qd] = *(const float4*)(x + (size_t)(n*CC + c)*(TT*VV) + t0*VV + qd*4);
    }

    // ---- v-stage lane constants (octet q, half h) ----
    int q = w & 3, h = w >> 2;
    bool hasB = (lane < 18);
    int offA = 100*h + 2*lane;
    int offB = hasB ? (offA + 64) : offA;
    int tvA  = offA;
    int tvB  = offA + 64;
    int sA0 = (tvA % VV)*VTS + tvA/VV;
    int sA1 = ((tvA+1) % VV)*VTS + (tvA+1)/VV;
    int sB0 = hasB ? ((tvB % VV)*VTS + tvB/VV) : 0;
    int sB1 = hasB ? (((tvB+1) % VV)*VTS + (tvB+1)/VV) : 0;

    // ---- y-stage lane constants ----
    int tp = lane >> 3, ug = lane & 7;

    // persistent y acc (f32x2 over u-pairs), init with ybias
    ull acc2[4][2][2];
    #pragma unroll
    for (int oq = 0; oq < 4; oq++) {
        const float* yb = g_ybias + (size_t)(n*OO + obase + 4*w + oq)*VV;
        #pragma unroll
        for (int p = 0; p < 2; p++) {
            int u0 = 4*ug + 2*p;
            float y0 = (u0   < VV) ? yb[u0]   : 0.f;
            float y1 = (u0+1 < VV) ? yb[u0+1] : 0.f;
            ull ybp = pk2(y0, y1);
            acc2[oq][0][p] = ybp; acc2[oq][1][p] = ybp;
        }
    }
    __syncthreads();

    for (int s = 0; s < SS; s++) {
        // ---- v-stage: 8 o's x 2 tv-pairs; w3 via constant port ----
        ull acc[8][2];
        #pragma unroll
        for (int i = 0; i < 8; i++) { acc[i][0] = 0ull; acc[i][1] = 0ull; }

        int wbase = (s*CC)*OO + obase + 8*q;
        #pragma unroll 4
        for (int c = 0; c < CC; c++) {
            float4 wA4 = *(const float4*)(c_w3t + wbase + c*OO);
            float4 wB4 = *(const float4*)(c_w3t + wbase + c*OO + 4);
            const float* xr = xs + c*TVW;
            ull xA = *(const ull*)(xr + offA);
            ull xB = *(const ull*)(xr + offB);
            ull w0 = pk2(wA4.x, wA4.x), w1 = pk2(wA4.y, wA4.y);
            ull w2 = pk2(wA4.z, wA4.z), w3s = pk2(wA4.w, wA4.w);
            ull w4s = pk2(wB4.x, wB4.x), w5 = pk2(wB4.y, wB4.y);
            ull w6 = pk2(wB4.z, wB4.z), w7 = pk2(wB4.w, wB4.w);
            acc[0][0]=fma2(w0,xA,acc[0][0]);  acc[0][1]=fma2(w0,xB,acc[0][1]);
            acc[1][0]=fma2(w1,xA,acc[1][0]);  acc[1][1]=fma2(w1,xB,acc[1][1]);
            acc[2][0]=fma2(w2,xA,acc[2][0]);  acc[2][1]=fma2(w2,xB,acc[2][1]);
            acc[3][0]=fma2(w3s,xA,acc[3][0]); acc[3][1]=fma2(w3s,xB,acc[3][1]);
            acc[4][0]=fma2(w4s,xA,acc[4][0]); acc[4][1]=fma2(w4s,xB,acc[4][1]);
            acc[5][0]=fma2(w5,xA,acc[5][0]);  acc[5][1]=fma2(w5,xB,acc[5][1]);
            acc[6][0]=fma2(w6,xA,acc[6][0]);  acc[6][1]=fma2(w6,xB,acc[6][1]);
            acc[7][0]=fma2(w7,xA,acc[7][0]);  acc[7][1]=fma2(w7,xB,acc[7][1]);
        }

        __syncthreads();   // prior y-stage reads of vt complete
        // ---- dump vT[o_loc][v][t] ----
        #pragma unroll
        for (int i = 0; i < 8; i++) {
            float* d = vt + (8*q + i) * OSTR;
            float lo, hi;
            upk2(acc[i][0], lo, hi);
            d[sA0] = lo; d[sA1] = hi;
            if (hasB) {
                upk2(acc[i][1], lo, hi);
                d[sB0] = lo; d[sB1] = hi;
            }
        }
        __syncthreads();

        // ---- y-stage: all 4 oq interleaved -> 4 independent att streams ----
        const float* dvp0 = vt + (4*w + 0)*OSTR + 2*tp;
        const float* dvp1 = vt + (4*w + 1)*OSTR + 2*tp;
        const float* dvp2 = vt + (4*w + 2)*OSTR + 2*tp;
        const float* dvp3 = vt + (4*w + 3)*OSTR + 2*tp;
        const float* agb = g_att + (size_t)((n*SS + s)*OO + obase + 4*w)*AOS + 4*ug;
        #pragma unroll
        for (int v = 0; v < VV; v++) {
            ulonglong2 at0 = *(const ulonglong2*)(agb + 0*AOS + v*UPAD);
            ulonglong2 at1 = *(const ulonglong2*)(agb + 1*AOS + v*UPAD);
            ulonglong2 at2 = *(const ulonglong2*)(agb + 2*AOS + v*UPAD);
            ulonglong2 at3 = *(const ulonglong2*)(agb + 3*AOS + v*UPAD);
            float2 vb0 = *(const float2*)(dvp0 + v*VTS);
            float2 vb1 = *(const float2*)(dvp1 + v*VTS);
            float2 vb2 = *(const float2*)(dvp2 + v*VTS);
            float2 vb3 = *(const float2*)(dvp3 + v*VTS);

            ull va, vbb;
            va = pk2(vb0.x, vb0.x); vbb = pk2(vb0.y, vb0.y);
            acc2[0][0][0] = fma2(at0.x, va,  acc2[0][0][0]);
            acc2[0][0][1] = fma2(at0.y, va,  acc2[0][0][1]);
            acc2[0][1][0] = fma2(at0.x, vbb, acc2[0][1][0]);
            acc2[0][1][1] = fma2(at0.y, vbb, acc2[0][1][1]);
            va = pk2(vb1.x, vb1.x); vbb = pk2(vb1.y, vb1.y);
            acc2[1][0][0] = fma2(at1.x, va,  acc2[1][0][0]);
            acc2[1][0][1] = fma2(at1.y, va,  acc2[1][0][1]);
            acc2[1][1][0] = fma2(at1.x, vbb, acc2[1][1][0]);
            acc2[1][1][1] = fma2(at1.y, vbb, acc2[1][1][1]);
            va = pk2(vb2.x, vb2.x); vbb = pk2(vb2.y, vb2.y);
            acc2[2][0][0] = fma2(at2.x, va,  acc2[2][0][0]);
            acc2[2][0][1] = fma2(at2.y, va,  acc2[2][0][1]);
            acc2[2][1][0] = fma2(at2.x, vbb, acc2[2][1][0]);
            acc2[2][1][1] = fma2(at2.y, vbb, acc2[2][1][1]);
            va = pk2(vb3.x, vb3.x); vbb = pk2(vb3.y, vb3.y);
            acc2[3][0][0] = fma2(at3.x, va,  acc2[3][0][0]);
            acc2[3][0][1] = fma2(at3.y, va,  acc2[3][0][1]);
            acc2[3][1][0] = fma2(at3.x, vbb, acc2[3][1][0]);
            acc2[3][1][1] = fma2(at3.y, vbb, acc2[3][1][1]);
        }
    }

    // ---- epilogue: write y (fp16), accumulate BN stats (fp32 exact) ----
    #pragma unroll
    for (int oq = 0; oq < 4; oq++) {
        int o = obase + 4*w + oq;
        float ps = 0.f, pss = 0.f;
        #pragma unroll
        for (int j = 0; j < 2; j++) {
            int t = 2*tp + j;
            float uv0, uv1, uv2, uv3;
            upk2(acc2[oq][j][0], uv0, uv1);
            upk2(acc2[oq][j][1], uv2, uv3);
            float vals[4] = {uv0, uv1, uv2, uv3};
            __half* yp = g_yh + ((size_t)(n*OO + o)*TT + t0 + t)*VV;
            #pragma unroll
            for (int i = 0; i < 4; i++) {
                int u = 4*ug + i;
                if (u < VV) {
                    yp[u] = __float2half(vals[i]);
                    ps  += vals[i];
                    pss += vals[i]*vals[i];
                }
            }
        }
        #pragma unroll
        for (int off = 16; off > 0; off >>= 1) {
            ps  += __shfl_xor_sync(0xffffffffu, ps,  off);
            pss += __shfl_xor_sync(0xffffffffu, pss, off);
        }
        if (lane == 0) {
            atomicAdd(&g_sum[o],   ps);
            atomicAdd(&g_sumsq[o], pss);
        }
    }
}

// ---------------------------------------------------------------------------
// Kernel 5 (k_bnp folded in): out = relu(y) + y*scale + shift + x.
// Each block derives scale/shift from global stats in smem (removes a node).
// y read as fp16 (flat 8B loads: 4 halves per out-float4).
// ---------------------------------------------------------------------------
__global__ void k_final(const float* __restrict__ x, float* __restrict__ out,
                        const float* __restrict__ gamma, const float* __restrict__ beta) {
    __shared__ float s_sc[OO], s_sh[OO];
    int tid = threadIdx.x;
    if (tid < OO) {
        float cnt = (float)(NN*TT*VV);
        float mu  = g_sum[tid] / cnt;
        float var = g_sumsq[tid] / cnt - mu*mu;
        float sc  = gamma[tid] * rsqrtf(var + EPSV);
        s_sc[tid] = sc;
        s_sh[tid] = beta[tid] - mu*sc;
    }
    __syncthreads();

    const int total4 = NN*OO*TT*VV / 4;
    for (int i = blockIdx.x*blockDim.x + tid; i < total4; i += gridDim.x*blockDim.x) {
        int c = (i / (TT*VV/4)) % OO;
        float sc = s_sc[c], sh = s_sh[c];
        uint2 raw = ((const uint2*)g_yh)[i];      // 4 halves, 8B aligned
        __half2 h0 = *reinterpret_cast<__half2*>(&raw.x);
        __half2 h1 = *reinterpret_cast<__half2*>(&raw.y);
        float2 f0 = __half22float2(h0);
        float2 f1 = __half22float2(h1);
        float4 x4 = ((const float4*)x)[i];
        float4 r;
        r.x = fmaxf(f0.x, 0.f) + fmaf(f0.x, sc, sh) + x4.x;
        r.y = fmaxf(f0.y, 0.f) + fmaf(f0.y, sc, sh) + x4.y;
        r.z = fmaxf(f1.x, 0.f) + fmaf(f1.x, sc, sh) + x4.z;
        r.w = fmaxf(f1.y, 0.f) + fmaf(f1.y, sc, sh) + x4.w;
        ((float4*)out)[i] = r;
    }
}

// ---------------------------------------------------------------------------
extern "C" void kernel_launch(void* const* d_in, const int* in_sizes, int n_in,
                              void* d_out, int out_size) {
    (void)in_sizes; (void)n_in; (void)out_size;
    const float* x     = (const float*)d_in[0];
    const float* A     = (const float*)d_in[1];
    const float* w1    = (const float*)d_in[2];
    const float* b1    = (const float*)d_in[3];
    const float* w2    = (const float*)d_in[4];
    const float* b2    = (const float*)d_in[5];
    const float* w3    = (const float*)d_in[6];
    const float* b3    = (const float*)d_in[7];
    const float* w4    = (const float*)d_in[8];
    const float* b4    = (const float*)d_in[9];
    const float* alpha = (const float*)d_in[10];
    const float* gamma = (const float*)d_in[11];
    const float* beta  = (const float*)d_in[12];
    float* out = (float*)d_out;

    static const int smem_bytes = SMEM_FLOATS * (int)sizeof(float);
    cudaFuncSetAttribute(k_main, cudaFuncAttributeMaxDynamicSharedMemorySize, smem_bytes);

    void* w3t_dev = nullptr;
    cudaGetSymbolAddress(&w3t_dev, g_w3t);

    k_xm   <<< NN*CC, 256 >>>(x, w3);
    cudaMemcpyToSymbolAsync(c_w3t, w3t_dev, SS*CC*OO*sizeof(float), 0,
                            cudaMemcpyDeviceToDevice, 0);
    k_att  <<< NN*SS*4, 256 >>>(w1, b1, w2, b2, w4, b4, alpha, A);
    k_ybias<<< NN*8, 256 >>>(b3);
    k_main <<< NN*NTB*2, 256, smem_bytes >>>(x);
    k_final<<< 4096, 256 >>>(x, out, gamma, beta);
}